// round 5
// baseline (speedup 1.0000x reference)
#include <cuda_runtime.h>
#include <cuda_fp16.h>

#define TT  30
#define TD  150
#define DIM 512
#define MAX_ROWS 34836   // WORDS_CNT + 1

// fp16 copy of the embedding table (zero-init .bss, no allocation)
__device__ __half g_w2v_h[(size_t)MAX_ROWS * DIM];

// ---- pass 1: fp32 -> fp16 table conversion (DRAM-read-bound) ---------------
__global__ __launch_bounds__(256)
void w2v_convert_kernel(const float4* __restrict__ src, uint2* __restrict__ dst, int n4)
{
    const int stride = gridDim.x * 256;
    int i = blockIdx.x * 256 + threadIdx.x;

    // unrolled grid-stride: 4 independent loads in flight per thread
    for (; i + 3 * stride < n4; i += 4 * stride) {
        float4 f0 = __ldcs(&src[i]);
        float4 f1 = __ldcs(&src[i + stride]);
        float4 f2 = __ldcs(&src[i + 2 * stride]);
        float4 f3 = __ldcs(&src[i + 3 * stride]);
        uint2 u0, u1, u2, u3;
        { __half2 a = __floats2half2_rn(f0.x, f0.y), b = __floats2half2_rn(f0.z, f0.w);
          u0.x = *(unsigned*)&a; u0.y = *(unsigned*)&b; }
        { __half2 a = __floats2half2_rn(f1.x, f1.y), b = __floats2half2_rn(f1.z, f1.w);
          u1.x = *(unsigned*)&a; u1.y = *(unsigned*)&b; }
        { __half2 a = __floats2half2_rn(f2.x, f2.y), b = __floats2half2_rn(f2.z, f2.w);
          u2.x = *(unsigned*)&a; u2.y = *(unsigned*)&b; }
        { __half2 a = __floats2half2_rn(f3.x, f3.y), b = __floats2half2_rn(f3.z, f3.w);
          u3.x = *(unsigned*)&a; u3.y = *(unsigned*)&b; }
        dst[i]              = u0;
        dst[i + stride]     = u1;
        dst[i + 2 * stride] = u2;
        dst[i + 3 * stride] = u3;
    }
    for (; i < n4; i += stride) {
        float4 f = __ldcs(&src[i]);
        __half2 a = __floats2half2_rn(f.x, f.y), b = __floats2half2_rn(f.z, f.w);
        uint2 u; u.x = *(unsigned*)&a; u.y = *(unsigned*)&b;
        dst[i] = u;
    }
}

// ---- pass 2: gather + pool ---------------------------------------------------
// 128 threads = 2 groups of 64. Group g processes tokens t ≡ g (mod 2).
// Each thread owns 8 dims (one LDG.128 of 8 halves per token).
__global__ __launch_bounds__(128, 12)
void swem_cat_kernel(const void* __restrict__ title_v,
                     const void* __restrict__ desc_v,
                     const void* __restrict__ tlen_v,
                     const void* __restrict__ dlen_v,
                     float* __restrict__ out)
{
    __shared__ int      s_idx[TT + TD];
    __shared__ int      s_len[2];
    __shared__ int      s_is64;
    __shared__ unsigned s_mxh[2 * 256];   // per-group max partials (half2)
    __shared__ float    s_smf[2 * 512];   // per-group sum partials (fp32)

    const int b    = blockIdx.x;
    const int tid  = threadIdx.x;
    const int g    = tid >> 6;      // token-parity group
    const int l64  = tid & 63;      // lane within group

    // dtype detection: int64 vs int32 indices (values < 34836 => high word 0)
    if (tid < 32) {
        unsigned hi  = ((const unsigned*)title_v)[2 * tid + 1];
        unsigned any = __ballot_sync(0xffffffffu, hi != 0u);
        if (tid == 0) s_is64 = (any == 0u) ? 1 : 0;
    }
    __syncthreads();

    if (s_is64) {
        const long long* tp = (const long long*)title_v + (long long)b * TT;
        const long long* dp = (const long long*)desc_v  + (long long)b * TD;
        if (tid < TT) s_idx[tid] = (int)tp[tid];
        for (int i = tid; i < TD; i += 128) s_idx[TT + i] = (int)dp[i];
        if (tid == 0) {
            s_len[0] = (int)((const long long*)tlen_v)[b];
            s_len[1] = (int)((const long long*)dlen_v)[b];
        }
    } else {
        const int* tp = (const int*)title_v + b * TT;
        const int* dp = (const int*)desc_v  + b * TD;
        if (tid < TT) s_idx[tid] = tp[tid];
        for (int i = tid; i < TD; i += 128) s_idx[TT + i] = dp[i];
        if (tid == 0) {
            s_len[0] = ((const int*)tlen_v)[b];
            s_len[1] = ((const int*)dlen_v)[b];
        }
    }
    __syncthreads();

    const int tl = s_len[0];
    const int dl = s_len[1];
    const __half* hbase = g_w2v_h + l64 * 8;          // this thread's 8-dim slice
    float* orow = out + (size_t)b * (4 * DIM);

    const unsigned NEGH2 = 0xFC00FC00u;               // (-inf, -inf) in half2

    // =========================== TITLE ======================================
    {
        unsigned mx0 = NEGH2, mx1 = NEGH2, mx2 = NEGH2, mx3 = NEGH2;
        float sm[8] = {0.f,0.f,0.f,0.f,0.f,0.f,0.f,0.f};

        #pragma unroll 4
        for (int t = g; t < tl; t += 2) {
            const uint4 u = *(const uint4*)(hbase + (size_t)s_idx[t] * DIM);
            __half2 h0 = *(const __half2*)&u.x, h1 = *(const __half2*)&u.y;
            __half2 h2 = *(const __half2*)&u.z, h3 = *(const __half2*)&u.w;
            __half2 m;
            m = __hmax2(*(__half2*)&mx0, h0); mx0 = *(unsigned*)&m;
            m = __hmax2(*(__half2*)&mx1, h1); mx1 = *(unsigned*)&m;
            m = __hmax2(*(__half2*)&mx2, h2); mx2 = *(unsigned*)&m;
            m = __hmax2(*(__half2*)&mx3, h3); mx3 = *(unsigned*)&m;
            float2 f;
            f = __half22float2(h0); sm[0] += f.x; sm[1] += f.y;
            f = __half22float2(h1); sm[2] += f.x; sm[3] += f.y;
            f = __half22float2(h2); sm[4] += f.x; sm[5] += f.y;
            f = __half22float2(h3); sm[6] += f.x; sm[7] += f.y;
        }
        // stage partials
        unsigned* mxp = s_mxh + g * 256 + l64 * 4;
        mxp[0] = mx0; mxp[1] = mx1; mxp[2] = mx2; mxp[3] = mx3;
        float* smp = s_smf + g * 512 + l64 * 8;
        #pragma unroll
        for (int k = 0; k < 8; k++) smp[k] = sm[k];
        __syncthreads();

        // merge: thread tid owns dims [4*tid, 4*tid+4)
        const int p = tid * 2;
        __half2 a0 = *(__half2*)&s_mxh[p],       a1 = *(__half2*)&s_mxh[p + 1];
        __half2 b0 = *(__half2*)&s_mxh[256 + p], b1 = *(__half2*)&s_mxh[256 + p + 1];
        __half2 m0 = __hmax2(a0, b0), m1 = __hmax2(a1, b1);
        float2 mf0 = __half22float2(m0), mf1 = __half22float2(m1);
        float4 mx4 = make_float4(mf0.x, mf0.y, mf1.x, mf1.y);
        const int q = tid * 4;
        float4 sm4 = make_float4(s_smf[q]     + s_smf[512 + q],
                                 s_smf[q + 1] + s_smf[512 + q + 1],
                                 s_smf[q + 2] + s_smf[512 + q + 2],
                                 s_smf[q + 3] + s_smf[512 + q + 3]);
        float4 av4;
        if (tl > 0) {
            const float inv = 1.0f / (float)tl;
            av4 = make_float4(sm4.x * inv, sm4.y * inv, sm4.z * inv, sm4.w * inv);
        } else {
            mx4 = make_float4(0.f, 0.f, 0.f, 0.f);
            av4 = make_float4(0.f, 0.f, 0.f, 0.f);
        }
        *(float4*)(orow + q)           = mx4;   // t_max  -> [0, 512)
        *(float4*)(orow + 2 * DIM + q) = av4;   // t_avg  -> [1024, 1536)
        __syncthreads();   // protect smem before desc reuses it
    }

    // =========================== DESC =======================================
    {
        unsigned mx0 = NEGH2, mx1 = NEGH2, mx2 = NEGH2, mx3 = NEGH2;
        float sm[8] = {0.f,0.f,0.f,0.f,0.f,0.f,0.f,0.f};

        #pragma unroll 4
        for (int t = g; t < dl; t += 2) {
            const uint4 u = *(const uint4*)(hbase + (size_t)s_idx[TT + t] * DIM);
            __half2 h0 = *(const __half2*)&u.x, h1 = *(const __half2*)&u.y;
            __half2 h2 = *(const __half2*)&u.z, h3 = *(const __half2*)&u.w;
            __half2 m;
            m = __hmax2(*(__half2*)&mx0, h0); mx0 = *(unsigned*)&m;
            m = __hmax2(*(__half2*)&mx1, h1); mx1 = *(unsigned*)&m;
            m = __hmax2(*(__half2*)&mx2, h2); mx2 = *(unsigned*)&m;
            m = __hmax2(*(__half2*)&mx3, h3); mx3 = *(unsigned*)&m;
            float2 f;
            f = __half22float2(h0); sm[0] += f.x; sm[1] += f.y;
            f = __half22float2(h1); sm[2] += f.x; sm[3] += f.y;
            f = __half22float2(h2); sm[4] += f.x; sm[5] += f.y;
            f = __half22float2(h3); sm[6] += f.x; sm[7] += f.y;
        }
        unsigned* mxp = s_mxh + g * 256 + l64 * 4;
        mxp[0] = mx0; mxp[1] = mx1; mxp[2] = mx2; mxp[3] = mx3;
        float* smp = s_smf + g * 512 + l64 * 8;
        #pragma unroll
        for (int k = 0; k < 8; k++) smp[k] = sm[k];
        __syncthreads();

        const int p = tid * 2;
        __half2 a0 = *(__half2*)&s_mxh[p],       a1 = *(__half2*)&s_mxh[p + 1];
        __half2 b0 = *(__half2*)&s_mxh[256 + p], b1 = *(__half2*)&s_mxh[256 + p + 1];
        __half2 m0 = __hmax2(a0, b0), m1 = __hmax2(a1, b1);
        float2 mf0 = __half22float2(m0), mf1 = __half22float2(m1);
        float4 mx4 = make_float4(mf0.x, mf0.y, mf1.x, mf1.y);
        const int q = tid * 4;
        float4 sm4 = make_float4(s_smf[q]     + s_smf[512 + q],
                                 s_smf[q + 1] + s_smf[512 + q + 1],
                                 s_smf[q + 2] + s_smf[512 + q + 2],
                                 s_smf[q + 3] + s_smf[512 + q + 3]);
        float4 av4;
        if (dl > 0) {
            const float inv = 1.0f / (float)dl;
            av4 = make_float4(sm4.x * inv, sm4.y * inv, sm4.z * inv, sm4.w * inv);
        } else {
            mx4 = make_float4(0.f, 0.f, 0.f, 0.f);
            av4 = make_float4(0.f, 0.f, 0.f, 0.f);
        }
        *(float4*)(orow + DIM + q)     = mx4;   // d_max  -> [512, 1024)
        *(float4*)(orow + 3 * DIM + q) = av4;   // d_avg  -> [1536, 2048)
    }
}

extern "C" void kernel_launch(void* const* d_in, const int* in_sizes, int n_in,
                              void* d_out, int out_size)
{
    const void* title = d_in[0];
    const void* desc  = d_in[1];
    const void* tlen  = d_in[2];
    const void* dlen  = d_in[3];
    const float* w2v  = (const float*)d_in[n_in - 1];
    float* out        = (float*)d_out;

    const int B = in_sizes[2];                        // t_len has B elements

    long long w2v_elems = in_sizes[n_in - 1];
    long long rows = w2v_elems / DIM;
    if (rows > MAX_ROWS) rows = MAX_ROWS;
    const int n4 = (int)(rows * (DIM / 4));           // float4 chunks

    __half* dsth;
    cudaGetSymbolAddress((void**)&dsth, g_w2v_h);     // address only, no alloc

    int cgrid = 148 * 8;                              // 1184 CTAs, ~4 outer iters
    w2v_convert_kernel<<<cgrid, 256>>>((const float4*)w2v, (uint2*)dsth, n4);
    swem_cat_kernel<<<B, 128>>>(title, desc, tlen, dlen, out);
}

// round 6
// speedup vs baseline: 1.1174x; 1.1174x over previous
#include <cuda_runtime.h>
#include <cuda_fp16.h>

#define TT  30
#define TD  150
#define DIM 512
#define MAX_ROWS 34836   // WORDS_CNT + 1

// fp16 copy of the embedding table (zero-init .bss, no allocation)
__device__ __half g_w2v_h[(size_t)MAX_ROWS * DIM];

// ---- pass 1: fp32 -> fp16 table conversion ----------------------------------
// DRAM/L2 latency bound: deep unroll for MLP, 4 CTAs/SM.
__global__ __launch_bounds__(256)
void w2v_convert_kernel(const float4* __restrict__ src, uint2* __restrict__ dst, int n4)
{
    const int stride = gridDim.x * 256;
    int i = blockIdx.x * 256 + threadIdx.x;

    for (; i + 7 * stride < n4; i += 8 * stride) {
        float4 f[8];
        #pragma unroll
        for (int k = 0; k < 8; k++) f[k] = __ldcs(&src[i + k * stride]);
        #pragma unroll
        for (int k = 0; k < 8; k++) {
            __half2 a = __floats2half2_rn(f[k].x, f[k].y);
            __half2 b = __floats2half2_rn(f[k].z, f[k].w);
            uint2 u;
            u.x = *reinterpret_cast<unsigned*>(&a);
            u.y = *reinterpret_cast<unsigned*>(&b);
            dst[i + k * stride] = u;
        }
    }
    for (; i < n4; i += stride) {
        float4 f = __ldcs(&src[i]);
        __half2 a = __floats2half2_rn(f.x, f.y), b = __floats2half2_rn(f.z, f.w);
        uint2 u; u.x = *(unsigned*)&a; u.y = *(unsigned*)&b;
        dst[i] = u;
    }
}

// ---- pass 2: gather + pool ----------------------------------------------------
// 64 threads per CTA, one batch row per CTA. Thread t owns dims [8t, 8t+8):
// one LDG.128 (8 halves) per token, hmax2 for max, fp32 for sums. No merges.
__global__ __launch_bounds__(64, 14)
void swem_cat_kernel(const void* __restrict__ title_v,
                     const void* __restrict__ desc_v,
                     const void* __restrict__ tlen_v,
                     const void* __restrict__ dlen_v,
                     float* __restrict__ out)
{
    __shared__ int s_off[TT + TD];   // pre-scaled byte offsets (idx * 1024)
    __shared__ int s_len[2];
    __shared__ int s_is64;

    const int b   = blockIdx.x;
    const int tid = threadIdx.x;

    // dtype detection: int64 vs int32 indices (values < 34836 => high word 0)
    if (tid < 32) {
        unsigned hi  = ((const unsigned*)title_v)[2 * tid + 1];
        unsigned any = __ballot_sync(0xffffffffu, hi != 0u);
        if (tid == 0) s_is64 = (any == 0u) ? 1 : 0;
    }
    __syncthreads();

    if (s_is64) {
        const long long* tp = (const long long*)title_v + (long long)b * TT;
        const long long* dp = (const long long*)desc_v  + (long long)b * TD;
        for (int i = tid; i < TT; i += 64) s_off[i]      = ((int)tp[i]) << 10;
        for (int i = tid; i < TD; i += 64) s_off[TT + i] = ((int)dp[i]) << 10;
        if (tid == 0) {
            s_len[0] = (int)((const long long*)tlen_v)[b];
            s_len[1] = (int)((const long long*)dlen_v)[b];
        }
    } else {
        const int* tp = (const int*)title_v + b * TT;
        const int* dp = (const int*)desc_v  + b * TD;
        for (int i = tid; i < TT; i += 64) s_off[i]      = tp[i] << 10;
        for (int i = tid; i < TD; i += 64) s_off[TT + i] = dp[i] << 10;
        if (tid == 0) {
            s_len[0] = ((const int*)tlen_v)[b];
            s_len[1] = ((const int*)dlen_v)[b];
        }
    }
    __syncthreads();

    const int tl = s_len[0];
    const int dl = s_len[1];
    const char* hbase = (const char*)g_w2v_h + tid * 16;  // thread's 8-dim slice
    float* orow = out + (size_t)b * (4 * DIM) + tid * 8;

    const __half2 NEGH2 = __halves2half2(__ushort_as_half(0xFC00),
                                         __ushort_as_half(0xFC00)); // (-inf,-inf)

    // =========================== TITLE ======================================
    {
        __half2 mx0 = NEGH2, mx1 = NEGH2, mx2 = NEGH2, mx3 = NEGH2;
        float sm0=0.f, sm1=0.f, sm2=0.f, sm3=0.f, sm4=0.f, sm5=0.f, sm6=0.f, sm7=0.f;

        #pragma unroll 4
        for (int t = 0; t < tl; t++) {
            const uint4 u = *(const uint4*)(hbase + s_off[t]);
            const __half2 h0 = *(const __half2*)&u.x, h1 = *(const __half2*)&u.y;
            const __half2 h2 = *(const __half2*)&u.z, h3 = *(const __half2*)&u.w;
            mx0 = __hmax2(mx0, h0); mx1 = __hmax2(mx1, h1);
            mx2 = __hmax2(mx2, h2); mx3 = __hmax2(mx3, h3);
            float2 f;
            f = __half22float2(h0); sm0 += f.x; sm1 += f.y;
            f = __half22float2(h1); sm2 += f.x; sm3 += f.y;
            f = __half22float2(h2); sm4 += f.x; sm5 += f.y;
            f = __half22float2(h3); sm6 += f.x; sm7 += f.y;
        }
        float4 mxa, mxb, ava, avb;
        if (tl > 0) {
            float2 m0 = __half22float2(mx0), m1 = __half22float2(mx1);
            float2 m2 = __half22float2(mx2), m3 = __half22float2(mx3);
            mxa = make_float4(m0.x, m0.y, m1.x, m1.y);
            mxb = make_float4(m2.x, m2.y, m3.x, m3.y);
            const float inv = 1.0f / (float)tl;
            ava = make_float4(sm0 * inv, sm1 * inv, sm2 * inv, sm3 * inv);
            avb = make_float4(sm4 * inv, sm5 * inv, sm6 * inv, sm7 * inv);
        } else {
            mxa = mxb = ava = avb = make_float4(0.f, 0.f, 0.f, 0.f);
        }
        *(float4*)(orow)               = mxa;   // t_max -> [0,512)
        *(float4*)(orow + 4)           = mxb;
        *(float4*)(orow + 2 * DIM)     = ava;   // t_avg -> [1024,1536)
        *(float4*)(orow + 2 * DIM + 4) = avb;
    }

    // =========================== DESC =======================================
    {
        __half2 mx0 = NEGH2, mx1 = NEGH2, mx2 = NEGH2, mx3 = NEGH2;
        float sm0=0.f, sm1=0.f, sm2=0.f, sm3=0.f, sm4=0.f, sm5=0.f, sm6=0.f, sm7=0.f;

        #pragma unroll 4
        for (int t = 0; t < dl; t++) {
            const uint4 u = *(const uint4*)(hbase + s_off[TT + t]);
            const __half2 h0 = *(const __half2*)&u.x, h1 = *(const __half2*)&u.y;
            const __half2 h2 = *(const __half2*)&u.z, h3 = *(const __half2*)&u.w;
            mx0 = __hmax2(mx0, h0); mx1 = __hmax2(mx1, h1);
            mx2 = __hmax2(mx2, h2); mx3 = __hmax2(mx3, h3);
            float2 f;
            f = __half22float2(h0); sm0 += f.x; sm1 += f.y;
            f = __half22float2(h1); sm2 += f.x; sm3 += f.y;
            f = __half22float2(h2); sm4 += f.x; sm5 += f.y;
            f = __half22float2(h3); sm6 += f.x; sm7 += f.y;
        }
        float4 mxa, mxb, ava, avb;
        if (dl > 0) {
            float2 m0 = __half22float2(mx0), m1 = __half22float2(mx1);
            float2 m2 = __half22float2(mx2), m3 = __half22float2(mx3);
            mxa = make_float4(m0.x, m0.y, m1.x, m1.y);
            mxb = make_float4(m2.x, m2.y, m3.x, m3.y);
            const float inv = 1.0f / (float)dl;
            ava = make_float4(sm0 * inv, sm1 * inv, sm2 * inv, sm3 * inv);
            avb = make_float4(sm4 * inv, sm5 * inv, sm6 * inv, sm7 * inv);
        } else {
            mxa = mxb = ava = avb = make_float4(0.f, 0.f, 0.f, 0.f);
        }
        *(float4*)(orow + DIM)         = mxa;   // d_max -> [512,1024)
        *(float4*)(orow + DIM + 4)     = mxb;
        *(float4*)(orow + 3 * DIM)     = ava;   // d_avg -> [1536,2048)
        *(float4*)(orow + 3 * DIM + 4) = avb;
    }
}

extern "C" void kernel_launch(void* const* d_in, const int* in_sizes, int n_in,
                              void* d_out, int out_size)
{
    const void* title = d_in[0];
    const void* desc  = d_in[1];
    const void* tlen  = d_in[2];
    const void* dlen  = d_in[3];
    const float* w2v  = (const float*)d_in[n_in - 1];
    float* out        = (float*)d_out;

    const int B = in_sizes[2];                        // t_len has B elements

    long long w2v_elems = in_sizes[n_in - 1];
    long long rows = w2v_elems / DIM;
    if (rows > MAX_ROWS) rows = MAX_ROWS;
    const int n4 = (int)(rows * (DIM / 4));           // float4 chunks

    __half* dsth;
    cudaGetSymbolAddress((void**)&dsth, g_w2v_h);     // address only, no alloc

    w2v_convert_kernel<<<592, 256>>>((const float4*)w2v, (uint2*)dsth, n4);
    swem_cat_kernel<<<B, 64>>>(title, desc, tlen, dlen, out);
}